// round 16
// baseline (speedup 1.0000x reference)
#include <cuda_runtime.h>

#define B        8
#define KN       768
#define BETA_N   192
#define NCOV     64
#define NPTS     256
#define C_OUT    128
#define HW_OUT   (256*256)
#define C_RES    64
#define HW_RES   (512*512)
#define C_FEAT   192
#define REND_ELEMS (B*C_OUT*NPTS)   // 262144
#define TILE     16
#define OHALF    64

typedef unsigned long long ull;

__device__ float g_unc[B * KN];
__device__ float g_coarse[(size_t)B * KN * C_OUT];       // [b][pt][c]
__device__ int   g_perm[B * KN];                         // locality-bucketed order

// ------------------------------------------------------------------
// Kernel P (prep): grid 8, block 256. y-bucket locality permutation.
// ------------------------------------------------------------------
__global__ void prep_kernel(const float* __restrict__ rand_over) {
    __shared__ int hist[256];
    __shared__ int scan[256];
    int b = blockIdx.x;
    int tid = threadIdx.x;

    hist[tid] = 0;
    __syncthreads();

    int bucket[3];
#pragma unroll
    for (int i = 0; i < 3; i++) {
        int t = i * 256 + tid;
        float py = __ldg(rand_over + ((size_t)b * KN + t) * 2 + 1);
        float gy = py * 256.0f - 0.5f;
        int y0 = (int)floorf(gy);
        bucket[i] = min(max(y0, 0), 255);
        atomicAdd(&hist[bucket[i]], 1);
    }
    __syncthreads();

    scan[tid] = hist[tid];
    __syncthreads();
    for (int d = 1; d < 256; d <<= 1) {
        int val = scan[tid];
        int add = (tid >= d) ? scan[tid - d] : 0;
        __syncthreads();
        scan[tid] = val + add;
        __syncthreads();
    }
    int excl = scan[tid] - hist[tid];
    __syncthreads();
    scan[tid] = excl;
    __syncthreads();

#pragma unroll
    for (int i = 0; i < 3; i++) {
        int t = i * 256 + tid;
        int pos = atomicAdd(&scan[bucket[i]], 1);
        g_perm[b * KN + pos] = t;
    }
}

// ------------------------------------------------------------------
// Kernel A (unc): grid (96, 8), block 256. Locality-permuted order.
// ------------------------------------------------------------------
__global__ void unc_kernel(const float* __restrict__ outp,
                           const float* __restrict__ rand_over) {
    int b   = blockIdx.y;
    int bx  = blockIdx.x;
    int tid = threadIdx.x;
    int warp = tid >> 5, lane = tid & 31;
    int p = __ldg(g_perm + b * KN + bx * 8 + warp);

    const float* rnd = rand_over + ((size_t)b * KN + p) * 2;
    float px = rnd[0], py = rnd[1];

    float gx = __fadd_rn(__fmul_rn(px, 256.0f), -0.5f);
    float gy = __fadd_rn(__fmul_rn(py, 256.0f), -0.5f);
    float x0f = floorf(gx), y0f = floorf(gy);
    float wx = __fadd_rn(gx, -x0f);
    float wy = __fadd_rn(gy, -y0f);
    int x0 = (int)x0f, y0 = (int)y0f;

    int   pix[4];
    float vld[4];
#pragma unroll
    for (int j = 0; j < 4; j++) {
        int xi = x0 + (j & 1), yi = y0 + (j >> 1);
        vld[j] = (xi >= 0 && xi < 256 && yi >= 0 && yi < 256) ? 1.0f : 0.0f;
        int cx = min(max(xi, 0), 255), cy = min(max(yi, 0), 255);
        pix[j] = cy * 256 + cx;
    }

    const float* ob = outp + (size_t)b * C_OUT * HW_OUT;
    float vals[16];
#pragma unroll
    for (int j = 0; j < 4; j++)
#pragma unroll
        for (int k = 0; k < 4; k++)
            vals[j * 4 + k] = __ldg(ob + (size_t)(lane + k * 32) * HW_OUT + pix[j]);

    {
        float omx = 1.0f - wx, omy = 1.0f - wy;
        float cw[4] = { omx * omy * vld[0], wx * omy * vld[1],
                        omx * wy  * vld[2], wx * wy  * vld[3] };
        float* cc = g_coarse + ((size_t)b * KN + p) * C_OUT + lane;
#pragma unroll
        for (int k = 0; k < 4; k++) {
            float r = vals[k] * cw[0];
            r = fmaf(vals[4 + k],  cw[1], r);
            r = fmaf(vals[8 + k],  cw[2], r);
            r = fmaf(vals[12 + k], cw[3], r);
            cc[k * 32] = r;
        }
    }

    float m1c[4], m2c[4];
#pragma unroll
    for (int j = 0; j < 4; j++) {
        float m1 = vals[j * 4], m2 = -3.4e38f;
#pragma unroll
        for (int k = 1; k < 4; k++) {
            float v  = vals[j * 4 + k];
            float hi = fmaxf(m1, v), lo = fminf(m1, v);
            m2 = fmaxf(m2, lo);
            m1 = hi;
        }
#pragma unroll
        for (int off = 16; off; off >>= 1) {
            float o1 = __shfl_xor_sync(0xffffffffu, m1, off);
            float o2 = __shfl_xor_sync(0xffffffffu, m2, off);
            float hi = fmaxf(m1, o1), lo = fminf(m1, o1);
            m2 = fmaxf(lo, fmaxf(m2, o2));
            m1 = hi;
        }
        m1c[j] = m1; m2c[j] = m2;
    }

    if (lane == 0) {
        float omx = __fadd_rn(1.0f, -wx);
        float omy = __fadd_rn(1.0f, -wy);
        float v0, t, og0, og1;
        v0 = __fmul_rn(m1c[0], vld[0]); t = __fmul_rn(__fmul_rn(v0, omx), omy); og0 = t;
        v0 = __fmul_rn(m1c[1], vld[1]); t = __fmul_rn(__fmul_rn(v0, wx),  omy); og0 = __fadd_rn(og0, t);
        v0 = __fmul_rn(m1c[2], vld[2]); t = __fmul_rn(__fmul_rn(v0, omx), wy);  og0 = __fadd_rn(og0, t);
        v0 = __fmul_rn(m1c[3], vld[3]); t = __fmul_rn(__fmul_rn(v0, wx),  wy);  og0 = __fadd_rn(og0, t);
        v0 = __fmul_rn(m2c[0], vld[0]); t = __fmul_rn(__fmul_rn(v0, omx), omy); og1 = t;
        v0 = __fmul_rn(m2c[1], vld[1]); t = __fmul_rn(__fmul_rn(v0, wx),  omy); og1 = __fadd_rn(og1, t);
        v0 = __fmul_rn(m2c[2], vld[2]); t = __fmul_rn(__fmul_rn(v0, omx), wy);  og1 = __fadd_rn(og1, t);
        v0 = __fmul_rn(m2c[3], vld[3]); t = __fmul_rn(__fmul_rn(v0, wx),  wy);  og1 = __fadd_rn(og1, t);
        g_unc[b * KN + p] = -__fadd_rn(og0, -og1);
    }
}

// ------------------------------------------------------------------
// Kernel B (fused sort+rend): grid (32, 8), block 512.
// blockIdx.x = tile(0..15)*2 + ohalf. 16 points x 64 outputs.
// smem: wsh 48KB + fshT 12KB + skey 8KB = 68KB -> 2 blocks/SM co-resident.
// ------------------------------------------------------------------
#define SMEM_BYTES ((C_FEAT*OHALF + TILE*C_FEAT) * 4 + 1024 * 8)

__device__ __forceinline__ void cxr(ull& a, ull& b, bool up) {
    ull mn = a < b ? a : b;
    ull mx = a < b ? b : a;
    a = up ? mn : mx;
    b = up ? mx : mn;
}

__global__ __launch_bounds__(512)
void rend_kernel(const float* __restrict__ outp,
                 const float* __restrict__ res2,
                 const float* __restrict__ rand_over,
                 const float* __restrict__ rand_cov,
                 const float* __restrict__ weight,
                 const float* __restrict__ bias,
                 float* __restrict__ dout) {
    extern __shared__ float sm[];
    float* wsh  = sm;                      // [c/4][o64][4] quad-major 48KB
    float* fshT = sm + C_FEAT * OHALF;     // [p][c] 12KB
    ull*   skey = (ull*)(fshT + TILE * C_FEAT);

    __shared__ int   offA[TILE][4], offB[TILE][4];
    __shared__ float wA[TILE][4],  wB[TILE][4];
    __shared__ int   selall[256];

    int b     = blockIdx.y;
    int tile  = blockIdx.x >> 1;           // 0..15
    int ohalf = blockIdx.x & 1;
    bool is_cov = (tile >= 12);
    int tid = threadIdx.x;

    // ---- stage weight half with inline quad transpose (overlaps sort) ----
    {
        const float4* w4 = (const float4*)weight;   // [o][rem], rem 0..47
        float4* d4 = (float4*)wsh;                  // [rem][o64]
#pragma unroll
        for (int i = 0; i < 6; i++) {
            int v = i * 512 + tid;                  // 0..3071
            int o_l = v / 48, rem = v - o_l * 48;
            d4[rem * 64 + o_l] = __ldg(w4 + (ohalf * OHALF + o_l) * 48 + rem);
        }
    }

    if (!is_cov) {
        // ---- register/shfl bitonic over 1024 keys (2/thread) ----
        ull v[2];
        int base = tid * 2;
        if (base < KN) {
            float2 u2 = *(const float2*)(g_unc + b * KN + base);
            float uu[2] = { u2.x, u2.y };
#pragma unroll
            for (int r = 0; r < 2; r++) {
                unsigned ub = __float_as_uint(uu[r]);
                ub = (ub & 0x80000000u) ? ~ub : (ub | 0x80000000u);
                ub = ~ub;
                v[r] = ((ull)ub << 32) | (unsigned)(base + r);
            }
        } else {
            v[0] = ~0ULL; v[1] = ~0ULL;
        }

        cxr(v[0], v[1], (tid & 1) == 0);
        for (int k = 4; k <= 1024; k <<= 1) {
            bool up = ((tid & (k >> 1)) == 0);
            for (int j = k >> 1; j >= 2; j >>= 1) {
                int d = j >> 1;
                bool keep_min = (((tid & d) == 0) == up);
                if (d <= 16) {
#pragma unroll
                    for (int r = 0; r < 2; r++) {
                        ull u = __shfl_xor_sync(0xffffffffu, v[r], d);
                        ull mn = v[r] < u ? v[r] : u;
                        ull mx = v[r] < u ? u : v[r];
                        v[r] = keep_min ? mn : mx;
                    }
                } else {
                    skey[tid * 2]     = v[0];
                    skey[tid * 2 + 1] = v[1];
                    __syncthreads();
                    int pt = (tid ^ d) * 2;
#pragma unroll
                    for (int r = 0; r < 2; r++) {
                        ull u = skey[pt + r];
                        ull mn = v[r] < u ? v[r] : u;
                        ull mx = v[r] < u ? u : v[r];
                        v[r] = keep_min ? mn : mx;
                    }
                    __syncthreads();
                }
            }
            cxr(v[0], v[1], up);
        }

        if (tid < 96) {
            selall[tid * 2]     = (int)(v[0] & 0xFFFFFFFFu);
            selall[tid * 2 + 1] = (int)(v[1] & 0xFFFFFFFFu);
        }
        __syncthreads();

        // ---- my 16 points: coords out (ohalf0) + res2 params ----
        if (tid < TILE) {
            int pidx = tile * TILE + tid;
            int idx = selall[pidx];
            float px = __ldg(rand_over + ((size_t)b * KN + idx) * 2 + 0);
            float py = __ldg(rand_over + ((size_t)b * KN + idx) * 2 + 1);
            if (ohalf == 0) {
                float* pts = dout + REND_ELEMS + ((size_t)b * NPTS + pidx) * 2;
                pts[0] = px; pts[1] = py;
            }
            float gx = px * 512.0f - 0.5f, gy = py * 512.0f - 0.5f;
            float xf = floorf(gx), yf = floorf(gy);
            int x0 = (int)xf, y0 = (int)yf;
            float fx = gx - xf, fy = gy - yf;
#pragma unroll
            for (int j = 0; j < 4; j++) {
                int xi = x0 + (j & 1), yi = y0 + (j >> 1);
                float vv = (xi >= 0 && xi < 512 && yi >= 0 && yi < 512) ? 1.0f : 0.0f;
                offB[tid][j] = min(max(yi, 0), 511) * 512 + min(max(xi, 0), 511);
                wB[tid][j]   = ((j & 1) ? fx : 1.0f - fx) * ((j >> 1) ? fy : 1.0f - fy) * vv;
            }
        }
        __syncthreads();

        // ---- gather features ----
        float4* f4 = (float4*)fshT;
        {
            int c4 = tid & 31, p = tid >> 5;
            const float4* src = (const float4*)(g_coarse
                              + ((size_t)b * KN + selall[tile * TILE + p]) * C_OUT);
            f4[p * 48 + c4] = __ldg(src + c4);
        }
#pragma unroll
        for (int i = 0; i < 2; i++) {
            int vv = i * 512 + tid;
            int c = vv & 63, p = vv >> 6;
            const float* plane = res2 + (size_t)(b * C_RES + c) * HW_RES;
            float r =        wB[p][0] * __ldg(plane + offB[p][0]);
            r = fmaf(wB[p][1], __ldg(plane + offB[p][1]), r);
            r = fmaf(wB[p][2], __ldg(plane + offB[p][2]), r);
            r = fmaf(wB[p][3], __ldg(plane + offB[p][3]), r);
            fshT[p * C_FEAT + C_OUT + c] = r;
        }
    } else {
        // ---- cov tile: direct gather ----
        if (tid < TILE) {
            int j2 = (tile - 12) * TILE + tid;
            float px = __ldg(rand_cov + ((size_t)b * NCOV + j2) * 2 + 0);
            float py = __ldg(rand_cov + ((size_t)b * NCOV + j2) * 2 + 1);
            if (ohalf == 0) {
                float* pts = dout + REND_ELEMS + ((size_t)b * NPTS + BETA_N + j2) * 2;
                pts[0] = px; pts[1] = py;
            }
            {
                float gx = px * 256.0f - 0.5f, gy = py * 256.0f - 0.5f;
                float xf = floorf(gx), yf = floorf(gy);
                int x0 = (int)xf, y0 = (int)yf;
                float fx = gx - xf, fy = gy - yf;
#pragma unroll
                for (int j = 0; j < 4; j++) {
                    int xi = x0 + (j & 1), yi = y0 + (j >> 1);
                    float vv = (xi >= 0 && xi < 256 && yi >= 0 && yi < 256) ? 1.0f : 0.0f;
                    offA[tid][j] = min(max(yi, 0), 255) * 256 + min(max(xi, 0), 255);
                    wA[tid][j]   = ((j & 1) ? fx : 1.0f - fx) * ((j >> 1) ? fy : 1.0f - fy) * vv;
                }
            }
            {
                float gx = px * 512.0f - 0.5f, gy = py * 512.0f - 0.5f;
                float xf = floorf(gx), yf = floorf(gy);
                int x0 = (int)xf, y0 = (int)yf;
                float fx = gx - xf, fy = gy - yf;
#pragma unroll
                for (int j = 0; j < 4; j++) {
                    int xi = x0 + (j & 1), yi = y0 + (j >> 1);
                    float vv = (xi >= 0 && xi < 512 && yi >= 0 && yi < 512) ? 1.0f : 0.0f;
                    offB[tid][j] = min(max(yi, 0), 511) * 512 + min(max(xi, 0), 511);
                    wB[tid][j]   = ((j & 1) ? fx : 1.0f - fx) * ((j >> 1) ? fy : 1.0f - fy) * vv;
                }
            }
        }
        __syncthreads();

#pragma unroll
        for (int i = 0; i < 4; i++) {
            int vv = i * 512 + tid;
            int c = vv & 127, p = vv >> 7;
            const float* plane = outp + (size_t)(b * C_OUT + c) * HW_OUT;
            float r =        wA[p][0] * __ldg(plane + offA[p][0]);
            r = fmaf(wA[p][1], __ldg(plane + offA[p][1]), r);
            r = fmaf(wA[p][2], __ldg(plane + offA[p][2]), r);
            r = fmaf(wA[p][3], __ldg(plane + offA[p][3]), r);
            fshT[p * C_FEAT + c] = r;
        }
#pragma unroll
        for (int i = 0; i < 2; i++) {
            int vv = i * 512 + tid;
            int c = vv & 63, p = vv >> 6;
            const float* plane = res2 + (size_t)(b * C_RES + c) * HW_RES;
            float r =        wB[p][0] * __ldg(plane + offB[p][0]);
            r = fmaf(wB[p][1], __ldg(plane + offB[p][1]), r);
            r = fmaf(wB[p][2], __ldg(plane + offB[p][2]), r);
            r = fmaf(wB[p][3], __ldg(plane + offB[p][3]), r);
            fshT[p * C_FEAT + C_OUT + c] = r;
        }
    }
    __syncthreads();

    // ---- GEMV: thread = (o = tid&63, pg = tid>>6 -> 2 points) ----
    int o = tid & 63, pg = tid >> 6;     // pg 0..7
    float acc0, acc1;
    float bv = __ldg(bias + ohalf * OHALF + o);
    acc0 = bv; acc1 = bv;

    const float*  fp = fshT + pg * 2 * C_FEAT;
    const float4* wq = (const float4*)wsh + o;
#pragma unroll 6
    for (int cq = 0; cq < C_FEAT / 4; cq++) {
        float4 w  = wq[cq * 64];
        float4 f0 = *(const float4*)(fp + cq * 4);
        float4 f1 = *(const float4*)(fp + C_FEAT + cq * 4);
        acc0 = fmaf(w.x, f0.x, acc0);
        acc0 = fmaf(w.y, f0.y, acc0);
        acc0 = fmaf(w.z, f0.z, acc0);
        acc0 = fmaf(w.w, f0.w, acc0);
        acc1 = fmaf(w.x, f1.x, acc1);
        acc1 = fmaf(w.y, f1.y, acc1);
        acc1 = fmaf(w.z, f1.z, acc1);
        acc1 = fmaf(w.w, f1.w, acc1);
    }

    float* rp = dout + ((size_t)b * C_OUT + ohalf * OHALF + o) * NPTS
              + tile * TILE + pg * 2;
    *(float2*)rp = make_float2(acc0, acc1);
}

// ------------------------------------------------------------------
extern "C" void kernel_launch(void* const* d_in, const int* in_sizes, int n_in,
                              void* d_out, int out_size) {
    (void)in_sizes; (void)n_in; (void)out_size;
    const float* res2      = (const float*)d_in[1];
    const float* outp      = (const float*)d_in[2];
    const float* rand_over = (const float*)d_in[3];
    const float* rand_cov  = (const float*)d_in[4];
    const float* weight    = (const float*)d_in[5];
    const float* bias      = (const float*)d_in[6];
    float* dout = (float*)d_out;

    prep_kernel<<<B, 256>>>(rand_over);
    unc_kernel<<<dim3(96, B), 256>>>(outp, rand_over);

    cudaFuncSetAttribute(rend_kernel, cudaFuncAttributeMaxDynamicSharedMemorySize,
                         SMEM_BYTES);
    rend_kernel<<<dim3(32, B), 512, SMEM_BYTES>>>(outp, res2, rand_over, rand_cov,
                                                  weight, bias, dout);
}

// round 17
// speedup vs baseline: 1.4847x; 1.4847x over previous
#include <cuda_runtime.h>

#define B        8
#define KN       768
#define BETA_N   192
#define NCOV     64
#define NPTS     256
#define C_OUT    128
#define HW_OUT   (256*256)
#define C_RES    64
#define HW_RES   (512*512)
#define C_FEAT   192
#define REND_ELEMS (B*C_OUT*NPTS)   // 262144
#define TILE     16

typedef unsigned long long ull;

__device__ float g_unc[B * KN];
__device__ float g_coarse[(size_t)B * KN * C_OUT];       // [b][pt][c]
__device__ float g_wQ[C_FEAT * C_OUT];                   // [c/4][o][4] quad-major
__device__ int   g_perm[B * KN];                         // locality-bucketed order

// ------------------------------------------------------------------
// Kernel P (prep): grid 8, block 256.
// Each block: 1/8 of weight quad-transform + its batch's y-bucket perm.
// ------------------------------------------------------------------
__global__ void prep_kernel(const float* __restrict__ rand_over,
                            const float* __restrict__ weight) {
    __shared__ int hist[256];
    __shared__ int scan[256];
    int b = blockIdx.x;
    int tid = threadIdx.x;

    // ---- 1/8 of weight transform: w[o][c] -> g_wQ[c/4][o][4] ----
    {
        const float4* w4 = (const float4*)weight;     // idx = o*48 + rem
        float4* q4 = (float4*)g_wQ;
#pragma unroll
        for (int i = 0; i < 3; i++) {
            int v = b * 768 + i * 256 + tid;          // 0..6143
            int o = v / 48, rem = v - o * 48;
            q4[rem * 128 + o] = __ldg(w4 + v);
        }
    }

    // ---- locality permutation: bucket by clamped y0 (256 buckets) ----
    hist[tid] = 0;
    __syncthreads();

    int bucket[3];
#pragma unroll
    for (int i = 0; i < 3; i++) {
        int t = i * 256 + tid;
        float py = __ldg(rand_over + ((size_t)b * KN + t) * 2 + 1);
        float gy = py * 256.0f - 0.5f;
        int y0 = (int)floorf(gy);
        bucket[i] = min(max(y0, 0), 255);
        atomicAdd(&hist[bucket[i]], 1);
    }
    __syncthreads();

    scan[tid] = hist[tid];
    __syncthreads();
    for (int d = 1; d < 256; d <<= 1) {
        int val = scan[tid];
        int add = (tid >= d) ? scan[tid - d] : 0;
        __syncthreads();
        scan[tid] = val + add;
        __syncthreads();
    }
    int excl = scan[tid] - hist[tid];
    __syncthreads();
    scan[tid] = excl;                   // bucket cursors
    __syncthreads();

#pragma unroll
    for (int i = 0; i < 3; i++) {
        int t = i * 256 + tid;
        int pos = atomicAdd(&scan[bucket[i]], 1);
        g_perm[b * KN + pos] = t;
    }
}

// ------------------------------------------------------------------
// Kernel A (unc): grid (96, 8), block 256. Locality-permuted order.
// ------------------------------------------------------------------
__global__ void unc_kernel(const float* __restrict__ outp,
                           const float* __restrict__ rand_over) {
    int b   = blockIdx.y;
    int bx  = blockIdx.x;
    int tid = threadIdx.x;
    int warp = tid >> 5, lane = tid & 31;
    int p = __ldg(g_perm + b * KN + bx * 8 + warp);

    const float* rnd = rand_over + ((size_t)b * KN + p) * 2;
    float px = rnd[0], py = rnd[1];

    float gx = __fadd_rn(__fmul_rn(px, 256.0f), -0.5f);
    float gy = __fadd_rn(__fmul_rn(py, 256.0f), -0.5f);
    float x0f = floorf(gx), y0f = floorf(gy);
    float wx = __fadd_rn(gx, -x0f);
    float wy = __fadd_rn(gy, -y0f);
    int x0 = (int)x0f, y0 = (int)y0f;

    int   pix[4];
    float vld[4];
#pragma unroll
    for (int j = 0; j < 4; j++) {
        int xi = x0 + (j & 1), yi = y0 + (j >> 1);
        vld[j] = (xi >= 0 && xi < 256 && yi >= 0 && yi < 256) ? 1.0f : 0.0f;
        int cx = min(max(xi, 0), 255), cy = min(max(yi, 0), 255);
        pix[j] = cy * 256 + cx;
    }

    const float* ob = outp + (size_t)b * C_OUT * HW_OUT;
    float vals[16];
#pragma unroll
    for (int j = 0; j < 4; j++)
#pragma unroll
        for (int k = 0; k < 4; k++)
            vals[j * 4 + k] = __ldg(ob + (size_t)(lane + k * 32) * HW_OUT + pix[j]);

    {
        float omx = 1.0f - wx, omy = 1.0f - wy;
        float cw[4] = { omx * omy * vld[0], wx * omy * vld[1],
                        omx * wy  * vld[2], wx * wy  * vld[3] };
        float* cc = g_coarse + ((size_t)b * KN + p) * C_OUT + lane;
#pragma unroll
        for (int k = 0; k < 4; k++) {
            float r = vals[k] * cw[0];
            r = fmaf(vals[4 + k],  cw[1], r);
            r = fmaf(vals[8 + k],  cw[2], r);
            r = fmaf(vals[12 + k], cw[3], r);
            cc[k * 32] = r;
        }
    }

    float m1c[4], m2c[4];
#pragma unroll
    for (int j = 0; j < 4; j++) {
        float m1 = vals[j * 4], m2 = -3.4e38f;
#pragma unroll
        for (int k = 1; k < 4; k++) {
            float v  = vals[j * 4 + k];
            float hi = fmaxf(m1, v), lo = fminf(m1, v);
            m2 = fmaxf(m2, lo);
            m1 = hi;
        }
#pragma unroll
        for (int off = 16; off; off >>= 1) {
            float o1 = __shfl_xor_sync(0xffffffffu, m1, off);
            float o2 = __shfl_xor_sync(0xffffffffu, m2, off);
            float hi = fmaxf(m1, o1), lo = fminf(m1, o1);
            m2 = fmaxf(lo, fmaxf(m2, o2));
            m1 = hi;
        }
        m1c[j] = m1; m2c[j] = m2;
    }

    if (lane == 0) {
        float omx = __fadd_rn(1.0f, -wx);
        float omy = __fadd_rn(1.0f, -wy);
        float v0, t, og0, og1;
        v0 = __fmul_rn(m1c[0], vld[0]); t = __fmul_rn(__fmul_rn(v0, omx), omy); og0 = t;
        v0 = __fmul_rn(m1c[1], vld[1]); t = __fmul_rn(__fmul_rn(v0, wx),  omy); og0 = __fadd_rn(og0, t);
        v0 = __fmul_rn(m1c[2], vld[2]); t = __fmul_rn(__fmul_rn(v0, omx), wy);  og0 = __fadd_rn(og0, t);
        v0 = __fmul_rn(m1c[3], vld[3]); t = __fmul_rn(__fmul_rn(v0, wx),  wy);  og0 = __fadd_rn(og0, t);
        v0 = __fmul_rn(m2c[0], vld[0]); t = __fmul_rn(__fmul_rn(v0, omx), omy); og1 = t;
        v0 = __fmul_rn(m2c[1], vld[1]); t = __fmul_rn(__fmul_rn(v0, wx),  omy); og1 = __fadd_rn(og1, t);
        v0 = __fmul_rn(m2c[2], vld[2]); t = __fmul_rn(__fmul_rn(v0, omx), wy);  og1 = __fadd_rn(og1, t);
        v0 = __fmul_rn(m2c[3], vld[3]); t = __fmul_rn(__fmul_rn(v0, wx),  wy);  og1 = __fadd_rn(og1, t);
        g_unc[b * KN + p] = -__fadd_rn(og0, -og1);
    }
}

// ------------------------------------------------------------------
// Kernel B (fused sort+rend): grid (16, 8), block 512.  (R15 verbatim)
// imp tiles: bitonic top-k + cached-coarse/res2 gather + GEMV.
// cov tiles: direct gather from out+res2 (overlaps imp sorts) + GEMV.
// ------------------------------------------------------------------
#define SMEM_BYTES ((C_FEAT*C_OUT + TILE*C_FEAT) * 4 + 1024 * 8)

__device__ __forceinline__ void cxr(ull& a, ull& b, bool up) {
    ull mn = a < b ? a : b;
    ull mx = a < b ? b : a;
    a = up ? mn : mx;
    b = up ? mx : mn;
}

__global__ __launch_bounds__(512)
void rend_kernel(const float* __restrict__ outp,
                 const float* __restrict__ res2,
                 const float* __restrict__ rand_over,
                 const float* __restrict__ rand_cov,
                 const float* __restrict__ bias,
                 float* __restrict__ dout) {
    extern __shared__ float sm[];
    float* wsh  = sm;                      // [c/4][o][4]  96 KB
    float* fshT = sm + C_FEAT * C_OUT;     // [p][c]       12 KB
    ull*   skey = (ull*)(fshT + TILE * C_FEAT);

    __shared__ int   offA[TILE][4], offB[TILE][4];
    __shared__ float wA[TILE][4],  wB[TILE][4];
    __shared__ int   selall[256];

    int b    = blockIdx.y;
    int tile = blockIdx.x;
    bool is_cov = (tile >= 12);
    int tid = threadIdx.x;

    // ---- stage quad-major weight verbatim (overlaps sort/gather) ----
    {
        const float4* w4 = (const float4*)g_wQ;
        float4* d4 = (float4*)wsh;
#pragma unroll
        for (int i = 0; i < 12; i++)
            d4[i * 512 + tid] = __ldg(w4 + i * 512 + tid);
    }

    if (!is_cov) {
        // ---- register/shfl bitonic over 1024 keys (2/thread) ----
        ull v[2];
        int base = tid * 2;
        if (base < KN) {
            float2 u2 = *(const float2*)(g_unc + b * KN + base);
            float uu[2] = { u2.x, u2.y };
#pragma unroll
            for (int r = 0; r < 2; r++) {
                unsigned ub = __float_as_uint(uu[r]);
                ub = (ub & 0x80000000u) ? ~ub : (ub | 0x80000000u);
                ub = ~ub;
                v[r] = ((ull)ub << 32) | (unsigned)(base + r);
            }
        } else {
            v[0] = ~0ULL; v[1] = ~0ULL;
        }

        cxr(v[0], v[1], (tid & 1) == 0);
        for (int k = 4; k <= 1024; k <<= 1) {
            bool up = ((tid & (k >> 1)) == 0);
            for (int j = k >> 1; j >= 2; j >>= 1) {
                int d = j >> 1;
                bool keep_min = (((tid & d) == 0) == up);
                if (d <= 16) {
#pragma unroll
                    for (int r = 0; r < 2; r++) {
                        ull u = __shfl_xor_sync(0xffffffffu, v[r], d);
                        ull mn = v[r] < u ? v[r] : u;
                        ull mx = v[r] < u ? u : v[r];
                        v[r] = keep_min ? mn : mx;
                    }
                } else {
                    skey[tid * 2]     = v[0];
                    skey[tid * 2 + 1] = v[1];
                    __syncthreads();
                    int pt = (tid ^ d) * 2;
#pragma unroll
                    for (int r = 0; r < 2; r++) {
                        ull u = skey[pt + r];
                        ull mn = v[r] < u ? v[r] : u;
                        ull mx = v[r] < u ? u : v[r];
                        v[r] = keep_min ? mn : mx;
                    }
                    __syncthreads();
                }
            }
            cxr(v[0], v[1], up);
        }

        if (tid < 96) {
            selall[tid * 2]     = (int)(v[0] & 0xFFFFFFFFu);
            selall[tid * 2 + 1] = (int)(v[1] & 0xFFFFFFFFu);
        }
        __syncthreads();

        // ---- my 16 points: coords out + res2 params ----
        if (tid < TILE) {
            int pidx = tile * TILE + tid;
            int idx = selall[pidx];
            float px = __ldg(rand_over + ((size_t)b * KN + idx) * 2 + 0);
            float py = __ldg(rand_over + ((size_t)b * KN + idx) * 2 + 1);
            float* pts = dout + REND_ELEMS + ((size_t)b * NPTS + pidx) * 2;
            pts[0] = px; pts[1] = py;

            float gx = px * 512.0f - 0.5f, gy = py * 512.0f - 0.5f;
            float xf = floorf(gx), yf = floorf(gy);
            int x0 = (int)xf, y0 = (int)yf;
            float fx = gx - xf, fy = gy - yf;
#pragma unroll
            for (int j = 0; j < 4; j++) {
                int xi = x0 + (j & 1), yi = y0 + (j >> 1);
                float vv = (xi >= 0 && xi < 512 && yi >= 0 && yi < 512) ? 1.0f : 0.0f;
                offB[tid][j] = min(max(yi, 0), 511) * 512 + min(max(xi, 0), 511);
                wB[tid][j]   = ((j & 1) ? fx : 1.0f - fx) * ((j >> 1) ? fy : 1.0f - fy) * vv;
            }
        }
        __syncthreads();

        // ---- gather features ----
        float4* f4 = (float4*)fshT;
        {
            int c4 = tid & 31, p = tid >> 5;
            const float4* src = (const float4*)(g_coarse
                              + ((size_t)b * KN + selall[tile * TILE + p]) * C_OUT);
            f4[p * 48 + c4] = __ldg(src + c4);
        }
#pragma unroll
        for (int i = 0; i < 2; i++) {
            int vv = i * 512 + tid;
            int c = vv & 63, p = vv >> 6;
            const float* plane = res2 + (size_t)(b * C_RES + c) * HW_RES;
            float r =        wB[p][0] * __ldg(plane + offB[p][0]);
            r = fmaf(wB[p][1], __ldg(plane + offB[p][1]), r);
            r = fmaf(wB[p][2], __ldg(plane + offB[p][2]), r);
            r = fmaf(wB[p][3], __ldg(plane + offB[p][3]), r);
            fshT[p * C_FEAT + C_OUT + c] = r;
        }
    } else {
        // ---- cov tile: direct gather (overlaps imp blocks' sorts) ----
        if (tid < TILE) {
            int j2 = (tile - 12) * TILE + tid;
            float px = __ldg(rand_cov + ((size_t)b * NCOV + j2) * 2 + 0);
            float py = __ldg(rand_cov + ((size_t)b * NCOV + j2) * 2 + 1);
            float* pts = dout + REND_ELEMS + ((size_t)b * NPTS + BETA_N + j2) * 2;
            pts[0] = px; pts[1] = py;
            {
                float gx = px * 256.0f - 0.5f, gy = py * 256.0f - 0.5f;
                float xf = floorf(gx), yf = floorf(gy);
                int x0 = (int)xf, y0 = (int)yf;
                float fx = gx - xf, fy = gy - yf;
#pragma unroll
                for (int j = 0; j < 4; j++) {
                    int xi = x0 + (j & 1), yi = y0 + (j >> 1);
                    float vv = (xi >= 0 && xi < 256 && yi >= 0 && yi < 256) ? 1.0f : 0.0f;
                    offA[tid][j] = min(max(yi, 0), 255) * 256 + min(max(xi, 0), 255);
                    wA[tid][j]   = ((j & 1) ? fx : 1.0f - fx) * ((j >> 1) ? fy : 1.0f - fy) * vv;
                }
            }
            {
                float gx = px * 512.0f - 0.5f, gy = py * 512.0f - 0.5f;
                float xf = floorf(gx), yf = floorf(gy);
                int x0 = (int)xf, y0 = (int)yf;
                float fx = gx - xf, fy = gy - yf;
#pragma unroll
                for (int j = 0; j < 4; j++) {
                    int xi = x0 + (j & 1), yi = y0 + (j >> 1);
                    float vv = (xi >= 0 && xi < 512 && yi >= 0 && yi < 512) ? 1.0f : 0.0f;
                    offB[tid][j] = min(max(yi, 0), 511) * 512 + min(max(xi, 0), 511);
                    wB[tid][j]   = ((j & 1) ? fx : 1.0f - fx) * ((j >> 1) ? fy : 1.0f - fy) * vv;
                }
            }
        }
        __syncthreads();

#pragma unroll
        for (int i = 0; i < 4; i++) {
            int vv = i * 512 + tid;
            int c = vv & 127, p = vv >> 7;
            const float* plane = outp + (size_t)(b * C_OUT + c) * HW_OUT;
            float r =        wA[p][0] * __ldg(plane + offA[p][0]);
            r = fmaf(wA[p][1], __ldg(plane + offA[p][1]), r);
            r = fmaf(wA[p][2], __ldg(plane + offA[p][2]), r);
            r = fmaf(wA[p][3], __ldg(plane + offA[p][3]), r);
            fshT[p * C_FEAT + c] = r;
        }
#pragma unroll
        for (int i = 0; i < 2; i++) {
            int vv = i * 512 + tid;
            int c = vv & 63, p = vv >> 6;
            const float* plane = res2 + (size_t)(b * C_RES + c) * HW_RES;
            float r =        wB[p][0] * __ldg(plane + offB[p][0]);
            r = fmaf(wB[p][1], __ldg(plane + offB[p][1]), r);
            r = fmaf(wB[p][2], __ldg(plane + offB[p][2]), r);
            r = fmaf(wB[p][3], __ldg(plane + offB[p][3]), r);
            fshT[p * C_FEAT + C_OUT + c] = r;
        }
    }
    __syncthreads();

    // ---- GEMV: thread = (o = tid&127, pg = tid>>7 -> 4 points) ----
    int o = tid & 127, pg = tid >> 7;
    float acc[4];
    float bv = __ldg(bias + o);
#pragma unroll
    for (int i = 0; i < 4; i++) acc[i] = bv;

    const float*  fp = fshT + pg * 4 * C_FEAT;
    const float4* wq = (const float4*)(wsh) + o;
#pragma unroll 4
    for (int cq = 0; cq < C_FEAT / 4; cq++) {
        float4 w = wq[cq * 128];
#pragma unroll
        for (int pp = 0; pp < 4; pp++) {
            float4 f = *(const float4*)(fp + pp * C_FEAT + cq * 4);
            float a = acc[pp];
            a = fmaf(w.x, f.x, a);
            a = fmaf(w.y, f.y, a);
            a = fmaf(w.z, f.z, a);
            a = fmaf(w.w, f.w, a);
            acc[pp] = a;
        }
    }

    float* rp = dout + ((size_t)b * C_OUT + o) * NPTS + tile * TILE + pg * 4;
    *(float4*)rp = make_float4(acc[0], acc[1], acc[2], acc[3]);
}

// ------------------------------------------------------------------
extern "C" void kernel_launch(void* const* d_in, const int* in_sizes, int n_in,
                              void* d_out, int out_size) {
    (void)in_sizes; (void)n_in; (void)out_size;
    const float* res2      = (const float*)d_in[1];
    const float* outp      = (const float*)d_in[2];
    const float* rand_over = (const float*)d_in[3];
    const float* rand_cov  = (const float*)d_in[4];
    const float* weight    = (const float*)d_in[5];
    const float* bias      = (const float*)d_in[6];
    float* dout = (float*)d_out;

    prep_kernel<<<B, 256>>>(rand_over, weight);
    unc_kernel<<<dim3(96, B), 256>>>(outp, rand_over);

    cudaFuncSetAttribute(rend_kernel, cudaFuncAttributeMaxDynamicSharedMemorySize,
                         SMEM_BYTES);
    rend_kernel<<<dim3(16, B), 512, SMEM_BYTES>>>(outp, res2, rand_over, rand_cov,
                                                  bias, dout);
}